// round 8
// baseline (speedup 1.0000x reference)
#include <cuda_runtime.h>
#include <cuda_fp16.h>
#include <math.h>

#define N_NODES 20000
#define NHID 128
#define HEADS 4
#define HC (HEADS * NHID)          // 512
#define E_EDGES 320000
#define ETOT (E_EDGES + N_NODES)   // 340000
#define NLAYERS 4
#define NCLASS 40
#define NEG_SLOPE 0.2f
#define DT 1.0f
#define ALPHA 1.0f
#define GAMMA 1.0f

// d_out layout: [out (N*NCLASS)] [X_all (N*(L+1)*C)] [Y_all (N*(L+1)*C)]
#define OUT_OFF   0
#define XALL_OFF  (N_NODES * NCLASS)
#define YALL_OFF  (XALL_OFF + N_NODES * (NLAYERS + 1) * NHID)
#define LSTRIDE   ((NLAYERS + 1) * NHID)

// ------------------------- device scratch (no allocs allowed) ----------------
__device__ __half g_hh[N_NODES * HC];        // fp16 messages
__device__ float g_X[N_NODES * NHID];
__device__ float g_Y[N_NODES * NHID];
__device__ float g_Xhi[N_NODES * NHID];      // tf32-split X (GEMM A input)
__device__ float g_Xlo[N_NODES * NHID];
__device__ float g_Whi[NHID * HC];           // tf32-split W (split once/call)
__device__ float g_Wlo[NHID * HC];
__device__ float g_as[N_NODES * HEADS];
__device__ float g_ad[N_NODES * HEADS];
__device__ int   g_deg[N_NODES];
__device__ int   g_cursor[N_NODES];
__device__ int   g_off[N_NODES + 1];
__device__ int   g_csr_src[ETOT];

__device__ __forceinline__ void cvt_split(float x, float& hi, float& lo) {
    unsigned h, l;
    asm("cvt.rna.tf32.f32 %0, %1;" : "=r"(h) : "f"(x));
    hi = __uint_as_float(h);
    float r = x - hi;
    asm("cvt.rna.tf32.f32 %0, %1;" : "=r"(l) : "f"(r));
    lo = __uint_as_float(l);
}

__device__ __forceinline__ void mma_tf32(float* c, const unsigned* a, const unsigned* b) {
    asm volatile(
        "mma.sync.aligned.m16n8k8.row.col.f32.tf32.tf32.f32 "
        "{%0,%1,%2,%3}, {%4,%5,%6,%7}, {%8,%9}, {%0,%1,%2,%3};\n"
        : "+f"(c[0]), "+f"(c[1]), "+f"(c[2]), "+f"(c[3])
        : "r"(a[0]), "r"(a[1]), "r"(a[2]), "r"(a[3]), "r"(b[0]), "r"(b[1]));
}

// ------------------------- setup kernels -------------------------------------
__global__ void k_zero_int2(int* a, int* b, int n) {
    int i = blockIdx.x * blockDim.x + threadIdx.x;
    if (i < n) { a[i] = 0; b[i] = 0; }
}

__global__ void k_count_deg(const int* __restrict__ dst) {
    int e = blockIdx.x * blockDim.x + threadIdx.x;
    if (e >= ETOT) return;
    int d = (e < E_EDGES) ? dst[e] : (e - E_EDGES);
    atomicAdd(&g_deg[d], 1);
}

__global__ void k_scan() {
    __shared__ int s[1024];
    const int CH = (N_NODES + 1023) / 1024;
    int tid = threadIdx.x;
    int base = tid * CH;
    int sum = 0;
    for (int i = 0; i < CH; i++) {
        int idx = base + i;
        if (idx < N_NODES) sum += g_deg[idx];
    }
    s[tid] = sum;
    __syncthreads();
    for (int d = 1; d < 1024; d <<= 1) {
        int v = (tid >= d) ? s[tid - d] : 0;
        __syncthreads();
        s[tid] += v;
        __syncthreads();
    }
    int run = (tid == 0) ? 0 : s[tid - 1];
    for (int i = 0; i < CH; i++) {
        int idx = base + i;
        if (idx < N_NODES) { g_off[idx] = run; run += g_deg[idx]; }
    }
    if (tid == 1023) g_off[N_NODES] = run;
}

__global__ void k_scatter(const int* __restrict__ src, const int* __restrict__ dst) {
    int e = blockIdx.x * blockDim.x + threadIdx.x;
    if (e >= ETOT) return;
    int d, s;
    if (e < E_EDGES) { d = dst[e]; s = src[e]; }
    else { d = e - E_EDGES; s = d; }
    int pos = g_off[d] + atomicAdd(&g_cursor[d], 1);
    g_csr_src[pos] = s;
}

// split W once per call
__global__ void k_splitW(const float* __restrict__ W) {
    int i = blockIdx.x * blockDim.x + threadIdx.x;   // 0..65535
    float hi, lo;
    cvt_split(W[i], hi, lo);
    g_Whi[i] = hi;
    g_Wlo[i] = lo;
}

// init state (+ split X) + write layer-0 slices of X_all / Y_all
__global__ void k_init(const float* __restrict__ x, float* __restrict__ out) {
    int n = blockIdx.x;
    int t = threadIdx.x;
    float v = x[n * NHID + t];
    g_X[n * NHID + t] = v;
    g_Y[n * NHID + t] = v;
    float hi, lo;
    cvt_split(v, hi, lo);
    g_Xhi[n * NHID + t] = hi;
    g_Xlo[n * NHID + t] = lo;
    out[XALL_OFF + n * LSTRIDE + t] = v;
    out[YALL_OFF + n * LSTRIDE + t] = v;
}

// ------------------------- 3xTF32 tensor-core GEMM + fused attention ----------
#define GBM 128
#define GBN 128
#define BK  32
#define AP  36
#define BP  136
#define A_T (128 * AP)
#define B_T (BK * BP)
#define GEMM_SMEM ((2 * A_T + 2 * B_T) * 4)   // 71680 B

__global__ __launch_bounds__(256) void k_gemm(const float* __restrict__ att_src,
                                              const float* __restrict__ att_dst) {
    extern __shared__ float sm[];
    float* Ahi = sm;
    float* Alo = Ahi + A_T;
    float* Bhi = Alo + A_T;
    float* Blo = Bhi + B_T;

    int tid = threadIdx.x;
    int m0 = blockIdx.y * GBM;
    int n0 = blockIdx.x * GBN;          // = head * NHID
    int head = blockIdx.x;
    int warp = tid >> 5, lane = tid & 31;
    int g = lane >> 2, q = lane & 3;
    int wm = (warp >> 1) * 32;
    int wn = (warp & 1) * 64;

    float acc[2][8][4];
#pragma unroll
    for (int mi = 0; mi < 2; mi++)
#pragma unroll
        for (int ni = 0; ni < 8; ni++)
#pragma unroll
            for (int j = 0; j < 4; j++) acc[mi][ni][j] = 0.f;

    const float4* Xhi4 = (const float4*)g_Xhi;
    const float4* Xlo4 = (const float4*)g_Xlo;
    const float4* Whi4 = (const float4*)g_Whi;
    const float4* Wlo4 = (const float4*)g_Wlo;

    for (int st = 0; st < 4; st++) {
        __syncthreads();
#pragma unroll
        for (int i = 0; i < 4; i++) {
            int idx = tid + i * 256;
            int r = idx >> 3, c4 = idx & 7;
            float4 vh = make_float4(0.f, 0.f, 0.f, 0.f);
            float4 vl = vh;
            if (m0 + r < N_NODES) {
                int gidx = (m0 + r) * 32 + st * 8 + c4;
                vh = Xhi4[gidx];
                vl = Xlo4[gidx];
            }
            ((float4*)(Ahi + r * AP))[c4] = vh;
            ((float4*)(Alo + r * AP))[c4] = vl;
        }
#pragma unroll
        for (int i = 0; i < 4; i++) {
            int idx = tid + i * 256;
            int kk = idx >> 5, c4 = idx & 31;
            int gidx = (st * 32 + kk) * (HC / 4) + (n0 >> 2) + c4;
            ((float4*)(Bhi + kk * BP))[c4] = Whi4[gidx];
            ((float4*)(Blo + kk * BP))[c4] = Wlo4[gidx];
        }
        __syncthreads();

#pragma unroll
        for (int ks = 0; ks < 4; ks++) {
            int k0 = ks * 8;
            unsigned ah[2][4], al[2][4];
#pragma unroll
            for (int mi = 0; mi < 2; mi++) {
                int r = wm + mi * 16 + g;
                ah[mi][0] = __float_as_uint(Ahi[r * AP + k0 + q]);
                ah[mi][1] = __float_as_uint(Ahi[(r + 8) * AP + k0 + q]);
                ah[mi][2] = __float_as_uint(Ahi[r * AP + k0 + 4 + q]);
                ah[mi][3] = __float_as_uint(Ahi[(r + 8) * AP + k0 + 4 + q]);
                al[mi][0] = __float_as_uint(Alo[r * AP + k0 + q]);
                al[mi][1] = __float_as_uint(Alo[(r + 8) * AP + k0 + q]);
                al[mi][2] = __float_as_uint(Alo[r * AP + k0 + 4 + q]);
                al[mi][3] = __float_as_uint(Alo[(r + 8) * AP + k0 + 4 + q]);
            }
#pragma unroll
            for (int ni = 0; ni < 8; ni++) {
                int c = wn + ni * 8 + g;
                unsigned bh[2], bl[2];
                bh[0] = __float_as_uint(Bhi[(k0 + q) * BP + c]);
                bh[1] = __float_as_uint(Bhi[(k0 + 4 + q) * BP + c]);
                bl[0] = __float_as_uint(Blo[(k0 + q) * BP + c]);
                bl[1] = __float_as_uint(Blo[(k0 + 4 + q) * BP + c]);
#pragma unroll
                for (int mi = 0; mi < 2; mi++) {
                    mma_tf32(acc[mi][ni], ah[mi], bh);
                    mma_tf32(acc[mi][ni], ah[mi], bl);
                    mma_tf32(acc[mi][ni], al[mi], bh);
                }
            }
        }
    }

    __syncthreads();
    float* sAs = Bhi;
    float* sAd = Bhi + 256;

    float attS[16], attD[16];
#pragma unroll
    for (int ni = 0; ni < 8; ni++) {
        int c = n0 + wn + ni * 8 + 2 * q;
        attS[2 * ni] = att_src[c];     attS[2 * ni + 1] = att_src[c + 1];
        attD[2 * ni] = att_dst[c];     attD[2 * ni + 1] = att_dst[c + 1];
    }
#pragma unroll
    for (int mi = 0; mi < 2; mi++) {
        float s1a = 0.f, s2a = 0.f, s1b = 0.f, s2b = 0.f;
#pragma unroll
        for (int ni = 0; ni < 8; ni++) {
            s1a += acc[mi][ni][0] * attS[2 * ni] + acc[mi][ni][1] * attS[2 * ni + 1];
            s2a += acc[mi][ni][0] * attD[2 * ni] + acc[mi][ni][1] * attD[2 * ni + 1];
            s1b += acc[mi][ni][2] * attS[2 * ni] + acc[mi][ni][3] * attS[2 * ni + 1];
            s2b += acc[mi][ni][2] * attD[2 * ni] + acc[mi][ni][3] * attD[2 * ni + 1];
        }
#pragma unroll
        for (int o = 2; o; o >>= 1) {
            s1a += __shfl_down_sync(0xffffffffu, s1a, o, 4);
            s2a += __shfl_down_sync(0xffffffffu, s2a, o, 4);
            s1b += __shfl_down_sync(0xffffffffu, s1b, o, 4);
            s2b += __shfl_down_sync(0xffffffffu, s2b, o, 4);
        }
        if (q == 0) {
            int half = warp & 1;
            int rA = wm + mi * 16 + g;
            sAs[half * 128 + rA] = s1a;      sAd[half * 128 + rA] = s2a;
            sAs[half * 128 + rA + 8] = s1b;  sAd[half * 128 + rA + 8] = s2b;
        }
    }
    __syncthreads();
    if (tid < 128) {
        int r = m0 + tid;
        if (r < N_NODES) {
            g_as[r * HEADS + head] = sAs[tid] + sAs[128 + tid];
            g_ad[r * HEADS + head] = sAd[tid] + sAd[128 + tid];
        }
    }

#pragma unroll
    for (int mi = 0; mi < 2; mi++) {
        int r = m0 + wm + mi * 16 + g;
#pragma unroll
        for (int ni = 0; ni < 8; ni++) {
            int c = n0 + wn + ni * 8 + 2 * q;
            if (r < N_NODES)
                *((__half2*)(g_hh + r * HC + c)) = __floats2half2_rn(acc[mi][ni][0], acc[mi][ni][1]);
            if (r + 8 < N_NODES)
                *((__half2*)(g_hh + (r + 8) * HC + c)) = __floats2half2_rn(acc[mi][ni][2], acc[mi][ni][3]);
        }
    }
}

// ------------------------- fused softmax + aggregate + GraphCON update --------
// WARP per node (8 nodes / 256-thread block). Lane owns 16 fp16 flat channels
// [16L..16L+15] (all in head L/8) -> out channels 4L..4L+3 register-local.
// Edge exp values computed 32-at-a-time in registers, broadcast via shfl.
// No shared memory, no block syncs.
__global__ __launch_bounds__(256) void k_aggregate(const float* __restrict__ bias,
                                                   float* __restrict__ out, int layer) {
    int warp = threadIdx.x >> 5, lane = threadIdx.x & 31;
    int n = blockIdx.x * 8 + warp;
    int hd = lane >> 3;
    int st = g_off[n], en = g_off[n + 1];
    float4 ad4 = ((const float4*)g_ad)[n];
    const uint4* h16 = (const uint4*)g_hh;   // 64 uint4 per row

    float acc[16];
#pragma unroll
    for (int i = 0; i < 16; i++) acc[i] = 0.f;
    float4 denp = make_float4(0.f, 0.f, 0.f, 0.f);

#define ACC8(base, u, e) { \
    float2 p0 = __half22float2(*(const __half2*)&(u).x); \
    float2 p1 = __half22float2(*(const __half2*)&(u).y); \
    float2 p2 = __half22float2(*(const __half2*)&(u).z); \
    float2 p3 = __half22float2(*(const __half2*)&(u).w); \
    acc[base+0] += (e) * p0.x; acc[base+1] += (e) * p0.y; \
    acc[base+2] += (e) * p1.x; acc[base+3] += (e) * p1.y; \
    acc[base+4] += (e) * p2.x; acc[base+5] += (e) * p2.y; \
    acc[base+6] += (e) * p3.x; acc[base+7] += (e) * p3.y; }

    for (int c0 = st; c0 < en; c0 += 32) {
        int cl = en - c0; if (cl > 32) cl = 32;
        // compute exp(leakyrelu(as+ad)) for up to 32 edges, one per lane
        int sreg = 0;
        float4 ex = make_float4(0.f, 0.f, 0.f, 0.f);
        if (lane < cl) {
            sreg = g_csr_src[c0 + lane];
            float4 as4 = ((const float4*)g_as)[sreg];
            float e0 = as4.x + ad4.x, e1 = as4.y + ad4.y;
            float e2 = as4.z + ad4.z, e3 = as4.w + ad4.w;
            e0 = e0 > 0.f ? e0 : e0 * NEG_SLOPE;
            e1 = e1 > 0.f ? e1 : e1 * NEG_SLOPE;
            e2 = e2 > 0.f ? e2 : e2 * NEG_SLOPE;
            e3 = e3 > 0.f ? e3 : e3 * NEG_SLOPE;
            ex = make_float4(__expf(e0), __expf(e1), __expf(e2), __expf(e3));
            denp.x += ex.x; denp.y += ex.y; denp.z += ex.z; denp.w += ex.w;
        }
        // gather-accumulate: broadcast edge j's (src, exp[hd]) to all lanes
        int j = 0;
        for (; j + 4 <= cl; j += 4) {
            int sj[4]; float ej[4]; uint4 ua[4], ub[4];
#pragma unroll
            for (int u = 0; u < 4; u++) {
                sj[u] = __shfl_sync(0xffffffffu, sreg, j + u);
                float fx = __shfl_sync(0xffffffffu, ex.x, j + u);
                float fy = __shfl_sync(0xffffffffu, ex.y, j + u);
                float fz = __shfl_sync(0xffffffffu, ex.z, j + u);
                float fw = __shfl_sync(0xffffffffu, ex.w, j + u);
                ej[u] = (hd == 0) ? fx : (hd == 1) ? fy : (hd == 2) ? fz : fw;
            }
#pragma unroll
            for (int u = 0; u < 4; u++) {
                const uint4* row = h16 + sj[u] * 64 + lane * 2;
                ua[u] = row[0]; ub[u] = row[1];
            }
#pragma unroll
            for (int u = 0; u < 4; u++) {
                ACC8(0, ua[u], ej[u])
                ACC8(8, ub[u], ej[u])
            }
        }
        for (; j < cl; j++) {
            int sj = __shfl_sync(0xffffffffu, sreg, j);
            float fx = __shfl_sync(0xffffffffu, ex.x, j);
            float fy = __shfl_sync(0xffffffffu, ex.y, j);
            float fz = __shfl_sync(0xffffffffu, ex.z, j);
            float fw = __shfl_sync(0xffffffffu, ex.w, j);
            float e = (hd == 0) ? fx : (hd == 1) ? fy : (hd == 2) ? fz : fw;
            const uint4* row = h16 + sj * 64 + lane * 2;
            uint4 ua = row[0], ub = row[1];
            ACC8(0, ua, e)
            ACC8(8, ub, e)
        }
    }
#undef ACC8

    // warp-reduce den (all lanes end with full sums of all 4 heads)
#pragma unroll
    for (int o = 16; o; o >>= 1) {
        denp.x += __shfl_xor_sync(0xffffffffu, denp.x, o);
        denp.y += __shfl_xor_sync(0xffffffffu, denp.y, o);
        denp.z += __shfl_xor_sync(0xffffffffu, denp.z, o);
        denp.w += __shfl_xor_sync(0xffffffffu, denp.w, o);
    }
    float den = (hd == 0) ? denp.x : (hd == 1) ? denp.y : (hd == 2) ? denp.z : denp.w;
    float inv = 1.0f / den;

    const float4* b4p = (const float4*)(bias + 16 * lane);
    float gg[16];
#pragma unroll
    for (int i4 = 0; i4 < 4; i4++) {
        float4 b = b4p[i4];
        gg[4 * i4 + 0] = acc[4 * i4 + 0] * inv + b.x;
        gg[4 * i4 + 1] = acc[4 * i4 + 1] * inv + b.y;
        gg[4 * i4 + 2] = acc[4 * i4 + 2] * inv + b.z;
        gg[4 * i4 + 3] = acc[4 * i4 + 3] * inv + b.w;
    }
#pragma unroll
    for (int i = 0; i < 16; i++)
        gg[i] = gg[i] > 0.f ? gg[i] : (expf(gg[i]) - 1.f);

    // out channels 4*lane + c, c=0..3 : mean of gg[4c..4c+3]
    float agg[4];
#pragma unroll
    for (int c = 0; c < 4; c++)
        agg[c] = 0.25f * (gg[4 * c] + gg[4 * c + 1] + gg[4 * c + 2] + gg[4 * c + 3]);

    float4 xv = ((const float4*)g_X)[n * 32 + lane];
    float4 yv = ((const float4*)g_Y)[n * 32 + lane];
    float4 y2, x2;
    y2.x = yv.x + DT * (agg[0] - ALPHA * yv.x - GAMMA * xv.x);
    y2.y = yv.y + DT * (agg[1] - ALPHA * yv.y - GAMMA * xv.y);
    y2.z = yv.z + DT * (agg[2] - ALPHA * yv.z - GAMMA * xv.z);
    y2.w = yv.w + DT * (agg[3] - ALPHA * yv.w - GAMMA * xv.w);
    x2.x = xv.x + DT * y2.x;
    x2.y = xv.y + DT * y2.y;
    x2.z = xv.z + DT * y2.z;
    x2.w = xv.w + DT * y2.w;
    ((float4*)g_X)[n * 32 + lane] = x2;
    ((float4*)g_Y)[n * 32 + lane] = y2;

    // presplit X for next layer's GEMM
    float4 hi4, lo4;
    cvt_split(x2.x, hi4.x, lo4.x);
    cvt_split(x2.y, hi4.y, lo4.y);
    cvt_split(x2.z, hi4.z, lo4.z);
    cvt_split(x2.w, hi4.w, lo4.w);
    ((float4*)g_Xhi)[n * 32 + lane] = hi4;
    ((float4*)g_Xlo)[n * 32 + lane] = lo4;

    float* xo = out + XALL_OFF + n * LSTRIDE + (layer + 1) * NHID + 4 * lane;
    float* yo = out + YALL_OFF + n * LSTRIDE + (layer + 1) * NHID + 4 * lane;
    *((float4*)xo) = x2;
    *((float4*)yo) = y2;
}

// ------------------------- output projection ----------------------------------
__global__ void k_outproj(const float* __restrict__ Wr, const float* __restrict__ br,
                          float* __restrict__ out) {
    __shared__ float xs[NHID];
    int n = blockIdx.x;
    int t = threadIdx.x;
    xs[t] = g_X[n * NHID + t];
    __syncthreads();
    if (t < NCLASS) {
        const float* w = Wr + t * NHID;
        float acc = 0.f;
#pragma unroll 8
        for (int k = 0; k < NHID; k++) acc += xs[k] * w[k];
        out[OUT_OFF + n * NCLASS + t] = acc + br[t];
    }
}

// ------------------------- launch ---------------------------------------------
extern "C" void kernel_launch(void* const* d_in, const int* in_sizes, int n_in,
                              void* d_out, int out_size) {
    const float* x       = (const float*)d_in[0];
    const int*   src     = (const int*)d_in[1];
    const int*   dst     = (const int*)d_in[2];
    const float* W       = (const float*)d_in[3];
    const float* att_src = (const float*)d_in[4];
    const float* att_dst = (const float*)d_in[5];
    const float* bias    = (const float*)d_in[6];
    const float* Wr      = (const float*)d_in[7];
    const float* br      = (const float*)d_in[8];
    float* out = (float*)d_out;

    cudaFuncSetAttribute(k_gemm, cudaFuncAttributeMaxDynamicSharedMemorySize, GEMM_SMEM);

    int *deg_p, *cur_p;
    cudaGetSymbolAddress((void**)&deg_p, g_deg);
    cudaGetSymbolAddress((void**)&cur_p, g_cursor);

    dim3 ggrid(HC / GBN, (N_NODES + GBM - 1) / GBM);   // (4, 157)

    // Launch order puts gemm in my 4th slot (targets the ncu capture window).
    // CSR build (count/scan/scatter) only needs to finish before the first
    // k_aggregate; gemm needs splitW + init.
    k_splitW<<<(NHID * HC) / 256, 256>>>(W);                         // 1
    k_init<<<N_NODES, NHID>>>(x, out);                               // 2
    k_zero_int2<<<(N_NODES + 255) / 256, 256>>>(deg_p, cur_p, N_NODES); // 3
    k_gemm<<<ggrid, 256, GEMM_SMEM>>>(att_src, att_dst);             // 4 (layer 0)
    k_count_deg<<<(ETOT + 255) / 256, 256>>>(dst);                   // 5
    k_scan<<<1, 1024>>>();                                           // 6
    k_scatter<<<(ETOT + 255) / 256, 256>>>(src, dst);                // 7
    k_aggregate<<<N_NODES / 8, 256>>>(bias, out, 0);                 // 8 (layer 0)

    for (int l = 1; l < NLAYERS; l++) {
        k_gemm<<<ggrid, 256, GEMM_SMEM>>>(att_src, att_dst);
        k_aggregate<<<N_NODES / 8, 256>>>(bias, out, l);
    }
    k_outproj<<<N_NODES, 128>>>(Wr, br, out);
}

// round 9
// speedup vs baseline: 1.1193x; 1.1193x over previous
#include <cuda_runtime.h>
#include <cuda_fp16.h>
#include <math.h>

#define N_NODES 20000
#define NHID 128
#define HEADS 4
#define HC (HEADS * NHID)          // 512
#define E_EDGES 320000
#define ETOT (E_EDGES + N_NODES)   // 340000
#define NLAYERS 4
#define NCLASS 40
#define NEG_SLOPE 0.2f
#define DT 1.0f
#define ALPHA 1.0f
#define GAMMA 1.0f

// d_out layout: [out (N*NCLASS)] [X_all (N*(L+1)*C)] [Y_all (N*(L+1)*C)]
#define OUT_OFF   0
#define XALL_OFF  (N_NODES * NCLASS)
#define YALL_OFF  (XALL_OFF + N_NODES * (NLAYERS + 1) * NHID)
#define LSTRIDE   ((NLAYERS + 1) * NHID)

// ------------------------- device scratch (no allocs allowed) ----------------
__device__ __half g_hh[N_NODES * HC];        // fp16 messages
__device__ float g_X[N_NODES * NHID];
__device__ float g_Y[N_NODES * NHID];
__device__ float g_Xhi[N_NODES * NHID];      // tf32-split X (GEMM A input)
__device__ float g_Xlo[N_NODES * NHID];
__device__ float g_Whi[NHID * HC];           // tf32-split W (split once/call)
__device__ float g_Wlo[NHID * HC];
__device__ float g_as[N_NODES * HEADS];
__device__ float g_ad[N_NODES * HEADS];
__device__ int   g_deg[N_NODES];
__device__ int   g_cursor[N_NODES];
__device__ int   g_off[N_NODES + 1];
__device__ int   g_csr_src[ETOT];

__device__ __forceinline__ void cvt_split(float x, float& hi, float& lo) {
    unsigned h, l;
    asm("cvt.rna.tf32.f32 %0, %1;" : "=r"(h) : "f"(x));
    hi = __uint_as_float(h);
    float r = x - hi;
    asm("cvt.rna.tf32.f32 %0, %1;" : "=r"(l) : "f"(r));
    lo = __uint_as_float(l);
}

__device__ __forceinline__ void mma_tf32(float* c, const unsigned* a, const unsigned* b) {
    asm volatile(
        "mma.sync.aligned.m16n8k8.row.col.f32.tf32.tf32.f32 "
        "{%0,%1,%2,%3}, {%4,%5,%6,%7}, {%8,%9}, {%0,%1,%2,%3};\n"
        : "+f"(c[0]), "+f"(c[1]), "+f"(c[2]), "+f"(c[3])
        : "r"(a[0]), "r"(a[1]), "r"(a[2]), "r"(a[3]), "r"(b[0]), "r"(b[1]));
}

// ------------------------- setup kernels -------------------------------------
__global__ void k_zero_int2(int* a, int* b, int n) {
    int i = blockIdx.x * blockDim.x + threadIdx.x;
    if (i < n) { a[i] = 0; b[i] = 0; }
}

__global__ void k_count_deg(const int* __restrict__ dst) {
    int e = blockIdx.x * blockDim.x + threadIdx.x;
    if (e >= ETOT) return;
    int d = (e < E_EDGES) ? dst[e] : (e - E_EDGES);
    atomicAdd(&g_deg[d], 1);
}

__global__ void k_scan() {
    __shared__ int s[1024];
    const int CH = (N_NODES + 1023) / 1024;
    int tid = threadIdx.x;
    int base = tid * CH;
    int sum = 0;
    for (int i = 0; i < CH; i++) {
        int idx = base + i;
        if (idx < N_NODES) sum += g_deg[idx];
    }
    s[tid] = sum;
    __syncthreads();
    for (int d = 1; d < 1024; d <<= 1) {
        int v = (tid >= d) ? s[tid - d] : 0;
        __syncthreads();
        s[tid] += v;
        __syncthreads();
    }
    int run = (tid == 0) ? 0 : s[tid - 1];
    for (int i = 0; i < CH; i++) {
        int idx = base + i;
        if (idx < N_NODES) { g_off[idx] = run; run += g_deg[idx]; }
    }
    if (tid == 1023) g_off[N_NODES] = run;
}

__global__ void k_scatter(const int* __restrict__ src, const int* __restrict__ dst) {
    int e = blockIdx.x * blockDim.x + threadIdx.x;
    if (e >= ETOT) return;
    int d, s;
    if (e < E_EDGES) { d = dst[e]; s = src[e]; }
    else { d = e - E_EDGES; s = d; }
    int pos = g_off[d] + atomicAdd(&g_cursor[d], 1);
    g_csr_src[pos] = s;
}

// split W once per call
__global__ void k_splitW(const float* __restrict__ W) {
    int i = blockIdx.x * blockDim.x + threadIdx.x;   // 0..65535
    float hi, lo;
    cvt_split(W[i], hi, lo);
    g_Whi[i] = hi;
    g_Wlo[i] = lo;
}

// init state (+ split X) + write layer-0 slices of X_all / Y_all
__global__ void k_init(const float* __restrict__ x, float* __restrict__ out) {
    int n = blockIdx.x;
    int t = threadIdx.x;
    float v = x[n * NHID + t];
    g_X[n * NHID + t] = v;
    g_Y[n * NHID + t] = v;
    float hi, lo;
    cvt_split(v, hi, lo);
    g_Xhi[n * NHID + t] = hi;
    g_Xlo[n * NHID + t] = lo;
    out[XALL_OFF + n * LSTRIDE + t] = v;
    out[YALL_OFF + n * LSTRIDE + t] = v;
}

// ------------------------- 3xTF32 tensor-core GEMM + fused attention ----------
// 128x128 tile, BK=32, smem 71.7 KB; __launch_bounds__(256,2) caps regs at 128
// so 2 CTAs/SM co-reside (R8 ncu: 142 regs -> 1 CTA/SM, occ 12.4%, tensor 36%).
#define GBM 128
#define GBN 128
#define BK  32
#define AP  36
#define BP  136
#define A_T (128 * AP)
#define B_T (BK * BP)
#define GEMM_SMEM ((2 * A_T + 2 * B_T) * 4)   // 71680 B

__global__ __launch_bounds__(256, 2) void k_gemm(const float* __restrict__ att_src,
                                                 const float* __restrict__ att_dst) {
    extern __shared__ float sm[];
    float* Ahi = sm;
    float* Alo = Ahi + A_T;
    float* Bhi = Alo + A_T;
    float* Blo = Bhi + B_T;

    int tid = threadIdx.x;
    int m0 = blockIdx.y * GBM;
    int n0 = blockIdx.x * GBN;          // = head * NHID
    int head = blockIdx.x;
    int warp = tid >> 5, lane = tid & 31;
    int g = lane >> 2, q = lane & 3;
    int wm = (warp >> 1) * 32;
    int wn = (warp & 1) * 64;

    float acc[2][8][4];
#pragma unroll
    for (int mi = 0; mi < 2; mi++)
#pragma unroll
        for (int ni = 0; ni < 8; ni++)
#pragma unroll
            for (int j = 0; j < 4; j++) acc[mi][ni][j] = 0.f;

    const float4* Xhi4 = (const float4*)g_Xhi;
    const float4* Xlo4 = (const float4*)g_Xlo;
    const float4* Whi4 = (const float4*)g_Whi;
    const float4* Wlo4 = (const float4*)g_Wlo;

    for (int st = 0; st < 4; st++) {
        __syncthreads();
#pragma unroll
        for (int i = 0; i < 4; i++) {
            int idx = tid + i * 256;
            int r = idx >> 3, c4 = idx & 7;
            float4 vh = make_float4(0.f, 0.f, 0.f, 0.f);
            float4 vl = vh;
            if (m0 + r < N_NODES) {
                int gidx = (m0 + r) * 32 + st * 8 + c4;
                vh = Xhi4[gidx];
                vl = Xlo4[gidx];
            }
            ((float4*)(Ahi + r * AP))[c4] = vh;
            ((float4*)(Alo + r * AP))[c4] = vl;
        }
#pragma unroll
        for (int i = 0; i < 4; i++) {
            int idx = tid + i * 256;
            int kk = idx >> 5, c4 = idx & 31;
            int gidx = (st * 32 + kk) * (HC / 4) + (n0 >> 2) + c4;
            ((float4*)(Bhi + kk * BP))[c4] = Whi4[gidx];
            ((float4*)(Blo + kk * BP))[c4] = Wlo4[gidx];
        }
        __syncthreads();

#pragma unroll
        for (int ks = 0; ks < 4; ks++) {
            int k0 = ks * 8;
            unsigned ah[2][4], al[2][4];
#pragma unroll
            for (int mi = 0; mi < 2; mi++) {
                int r = wm + mi * 16 + g;
                ah[mi][0] = __float_as_uint(Ahi[r * AP + k0 + q]);
                ah[mi][1] = __float_as_uint(Ahi[(r + 8) * AP + k0 + q]);
                ah[mi][2] = __float_as_uint(Ahi[r * AP + k0 + 4 + q]);
                ah[mi][3] = __float_as_uint(Ahi[(r + 8) * AP + k0 + 4 + q]);
                al[mi][0] = __float_as_uint(Alo[r * AP + k0 + q]);
                al[mi][1] = __float_as_uint(Alo[(r + 8) * AP + k0 + q]);
                al[mi][2] = __float_as_uint(Alo[r * AP + k0 + 4 + q]);
                al[mi][3] = __float_as_uint(Alo[(r + 8) * AP + k0 + 4 + q]);
            }
#pragma unroll
            for (int ni = 0; ni < 8; ni++) {
                int c = wn + ni * 8 + g;
                unsigned bh[2], bl[2];
                bh[0] = __float_as_uint(Bhi[(k0 + q) * BP + c]);
                bh[1] = __float_as_uint(Bhi[(k0 + 4 + q) * BP + c]);
                bl[0] = __float_as_uint(Blo[(k0 + q) * BP + c]);
                bl[1] = __float_as_uint(Blo[(k0 + 4 + q) * BP + c]);
#pragma unroll
                for (int mi = 0; mi < 2; mi++) {
                    mma_tf32(acc[mi][ni], ah[mi], bh);
                    mma_tf32(acc[mi][ni], ah[mi], bl);
                    mma_tf32(acc[mi][ni], al[mi], bh);
                }
            }
        }
    }

    __syncthreads();
    float* sAs = Bhi;
    float* sAd = Bhi + 256;

    float attS[16], attD[16];
#pragma unroll
    for (int ni = 0; ni < 8; ni++) {
        int c = n0 + wn + ni * 8 + 2 * q;
        attS[2 * ni] = att_src[c];     attS[2 * ni + 1] = att_src[c + 1];
        attD[2 * ni] = att_dst[c];     attD[2 * ni + 1] = att_dst[c + 1];
    }
#pragma unroll
    for (int mi = 0; mi < 2; mi++) {
        float s1a = 0.f, s2a = 0.f, s1b = 0.f, s2b = 0.f;
#pragma unroll
        for (int ni = 0; ni < 8; ni++) {
            s1a += acc[mi][ni][0] * attS[2 * ni] + acc[mi][ni][1] * attS[2 * ni + 1];
            s2a += acc[mi][ni][0] * attD[2 * ni] + acc[mi][ni][1] * attD[2 * ni + 1];
            s1b += acc[mi][ni][2] * attS[2 * ni] + acc[mi][ni][3] * attS[2 * ni + 1];
            s2b += acc[mi][ni][2] * attD[2 * ni] + acc[mi][ni][3] * attD[2 * ni + 1];
        }
#pragma unroll
        for (int o = 2; o; o >>= 1) {
            s1a += __shfl_down_sync(0xffffffffu, s1a, o, 4);
            s2a += __shfl_down_sync(0xffffffffu, s2a, o, 4);
            s1b += __shfl_down_sync(0xffffffffu, s1b, o, 4);
            s2b += __shfl_down_sync(0xffffffffu, s2b, o, 4);
        }
        if (q == 0) {
            int half = warp & 1;
            int rA = wm + mi * 16 + g;
            sAs[half * 128 + rA] = s1a;      sAd[half * 128 + rA] = s2a;
            sAs[half * 128 + rA + 8] = s1b;  sAd[half * 128 + rA + 8] = s2b;
        }
    }
    __syncthreads();
    if (tid < 128) {
        int r = m0 + tid;
        if (r < N_NODES) {
            g_as[r * HEADS + head] = sAs[tid] + sAs[128 + tid];
            g_ad[r * HEADS + head] = sAd[tid] + sAd[128 + tid];
        }
    }

#pragma unroll
    for (int mi = 0; mi < 2; mi++) {
        int r = m0 + wm + mi * 16 + g;
#pragma unroll
        for (int ni = 0; ni < 8; ni++) {
            int c = n0 + wn + ni * 8 + 2 * q;
            if (r < N_NODES)
                *((__half2*)(g_hh + r * HC + c)) = __floats2half2_rn(acc[mi][ni][0], acc[mi][ni][1]);
            if (r + 8 < N_NODES)
                *((__half2*)(g_hh + (r + 8) * HC + c)) = __floats2half2_rn(acc[mi][ni][2], acc[mi][ni][3]);
        }
    }
}

// ------------------------- fused softmax + aggregate + GraphCON update --------
// R7's best-known aggregate: 64 threads/node; thread t owns fp16 flat channels
// [8t..8t+7] (head t/16). Edge loop unrolled x8 for MLP.
#define ACH 64
__global__ __launch_bounds__(64) void k_aggregate(const float* __restrict__ bias,
                                                  float* __restrict__ out, int layer) {
    __shared__ int   s_src[ACH];
    __shared__ float s_ex[ACH * 4];
    __shared__ float4 s_den[2];

    int n = blockIdx.x;
    int t = threadIdx.x;
    int hd = t >> 4;
    int wid = t >> 5, lane = t & 31;
    int st = g_off[n], en = g_off[n + 1];
    float4 ad4 = ((const float4*)g_ad)[n];
    const uint4* h16 = (const uint4*)g_hh;

    float4 denp = make_float4(0.f, 0.f, 0.f, 0.f);
    float a0 = 0.f, a1 = 0.f, a2 = 0.f, a3 = 0.f;
    float a4 = 0.f, a5 = 0.f, a6 = 0.f, a7 = 0.f;

#define ACCUM(u, e) { \
    float2 p0 = __half22float2(*(const __half2*)&u.x); \
    float2 p1 = __half22float2(*(const __half2*)&u.y); \
    float2 p2 = __half22float2(*(const __half2*)&u.z); \
    float2 p3 = __half22float2(*(const __half2*)&u.w); \
    a0 += e * p0.x; a1 += e * p0.y; a2 += e * p1.x; a3 += e * p1.y; \
    a4 += e * p2.x; a5 += e * p2.y; a6 += e * p3.x; a7 += e * p3.y; }

    for (int c0 = st; c0 < en; c0 += ACH) {
        int cl = en - c0; if (cl > ACH) cl = ACH;
        if (t < cl) {
            int s = g_csr_src[c0 + t];
            float4 as4 = ((const float4*)g_as)[s];
            float e0 = as4.x + ad4.x, e1 = as4.y + ad4.y;
            float e2 = as4.z + ad4.z, e3 = as4.w + ad4.w;
            e0 = e0 > 0.f ? e0 : e0 * NEG_SLOPE;
            e1 = e1 > 0.f ? e1 : e1 * NEG_SLOPE;
            e2 = e2 > 0.f ? e2 : e2 * NEG_SLOPE;
            e3 = e3 > 0.f ? e3 : e3 * NEG_SLOPE;
            float x0 = __expf(e0), x1 = __expf(e1), x2 = __expf(e2), x3 = __expf(e3);
            s_src[t] = s;
            ((float4*)s_ex)[t] = make_float4(x0, x1, x2, x3);
            denp.x += x0; denp.y += x1; denp.z += x2; denp.w += x3;
        }
        __syncthreads();
        int j = 0;
        for (; j + 8 <= cl; j += 8) {
            int ss[8]; float ee[8]; uint4 uu[8];
#pragma unroll
            for (int u = 0; u < 8; u++) {
                ss[u] = s_src[j + u];
                ee[u] = s_ex[(j + u) * 4 + hd];
            }
#pragma unroll
            for (int u = 0; u < 8; u++) uu[u] = h16[ss[u] * 64 + t];
#pragma unroll
            for (int u = 0; u < 8; u++) ACCUM(uu[u], ee[u])
        }
        for (; j < cl; j++) {
            int s = s_src[j];
            float e = s_ex[j * 4 + hd];
            uint4 u = h16[s * 64 + t];
            ACCUM(u, e)
        }
        __syncthreads();
    }
#undef ACCUM

#pragma unroll
    for (int o = 16; o; o >>= 1) {
        denp.x += __shfl_xor_sync(0xffffffffu, denp.x, o);
        denp.y += __shfl_xor_sync(0xffffffffu, denp.y, o);
        denp.z += __shfl_xor_sync(0xffffffffu, denp.z, o);
        denp.w += __shfl_xor_sync(0xffffffffu, denp.w, o);
    }
    if (lane == 0) s_den[wid] = denp;
    __syncthreads();
    float4 d0 = s_den[0], d1 = s_den[1];
    float dens[4] = {d0.x + d1.x, d0.y + d1.y, d0.z + d1.z, d0.w + d1.w};
    float inv = 1.0f / dens[hd];

    const float4* b4p = (const float4*)(bias + 8 * t);
    float4 b0 = b4p[0], b1 = b4p[1];
    float g0 = a0 * inv + b0.x, g1 = a1 * inv + b0.y;
    float g2 = a2 * inv + b0.z, g3 = a3 * inv + b0.w;
    float g4 = a4 * inv + b1.x, g5 = a5 * inv + b1.y;
    float g6 = a6 * inv + b1.z, g7 = a7 * inv + b1.w;
    g0 = g0 > 0.f ? g0 : (expf(g0) - 1.f);
    g1 = g1 > 0.f ? g1 : (expf(g1) - 1.f);
    g2 = g2 > 0.f ? g2 : (expf(g2) - 1.f);
    g3 = g3 > 0.f ? g3 : (expf(g3) - 1.f);
    g4 = g4 > 0.f ? g4 : (expf(g4) - 1.f);
    g5 = g5 > 0.f ? g5 : (expf(g5) - 1.f);
    g6 = g6 > 0.f ? g6 : (expf(g6) - 1.f);
    g7 = g7 > 0.f ? g7 : (expf(g7) - 1.f);
    float aggA = 0.25f * (g0 + g1 + g2 + g3);
    float aggB = 0.25f * (g4 + g5 + g6 + g7);

    float2 xv = *((const float2*)(g_X + n * NHID + 2 * t));
    float2 yv = *((const float2*)(g_Y + n * NHID + 2 * t));
    float y2a = yv.x + DT * (aggA - ALPHA * yv.x - GAMMA * xv.x);
    float y2b = yv.y + DT * (aggB - ALPHA * yv.y - GAMMA * xv.y);
    float x2a = xv.x + DT * y2a;
    float x2b = xv.y + DT * y2b;
    *((float2*)(g_X + n * NHID + 2 * t)) = make_float2(x2a, x2b);
    *((float2*)(g_Y + n * NHID + 2 * t)) = make_float2(y2a, y2b);
    // presplit X for next layer's GEMM
    float hiA, loA, hiB, loB;
    cvt_split(x2a, hiA, loA);
    cvt_split(x2b, hiB, loB);
    *((float2*)(g_Xhi + n * NHID + 2 * t)) = make_float2(hiA, hiB);
    *((float2*)(g_Xlo + n * NHID + 2 * t)) = make_float2(loA, loB);

    float* xo = out + XALL_OFF + n * LSTRIDE + (layer + 1) * NHID + 2 * t;
    float* yo = out + YALL_OFF + n * LSTRIDE + (layer + 1) * NHID + 2 * t;
    *((float2*)xo) = make_float2(x2a, x2b);
    *((float2*)yo) = make_float2(y2a, y2b);
}

// ------------------------- output projection ----------------------------------
__global__ void k_outproj(const float* __restrict__ Wr, const float* __restrict__ br,
                          float* __restrict__ out) {
    __shared__ float xs[NHID];
    int n = blockIdx.x;
    int t = threadIdx.x;
    xs[t] = g_X[n * NHID + t];
    __syncthreads();
    if (t < NCLASS) {
        const float* w = Wr + t * NHID;
        float acc = 0.f;
#pragma unroll 8
        for (int k = 0; k < NHID; k++) acc += xs[k] * w[k];
        out[OUT_OFF + n * NCLASS + t] = acc + br[t];
    }
}

// ------------------------- launch ---------------------------------------------
extern "C" void kernel_launch(void* const* d_in, const int* in_sizes, int n_in,
                              void* d_out, int out_size) {
    const float* x       = (const float*)d_in[0];
    const int*   src     = (const int*)d_in[1];
    const int*   dst     = (const int*)d_in[2];
    const float* W       = (const float*)d_in[3];
    const float* att_src = (const float*)d_in[4];
    const float* att_dst = (const float*)d_in[5];
    const float* bias    = (const float*)d_in[6];
    const float* Wr      = (const float*)d_in[7];
    const float* br      = (const float*)d_in[8];
    float* out = (float*)d_out;

    cudaFuncSetAttribute(k_gemm, cudaFuncAttributeMaxDynamicSharedMemorySize, GEMM_SMEM);

    int *deg_p, *cur_p;
    cudaGetSymbolAddress((void**)&deg_p, g_deg);
    cudaGetSymbolAddress((void**)&cur_p, g_cursor);

    dim3 ggrid(HC / GBN, (N_NODES + GBM - 1) / GBM);   // (4, 157)

    // gemm stays in capture slot 4 for ncu; CSR build only needed before agg.
    k_splitW<<<(NHID * HC) / 256, 256>>>(W);                         // 1
    k_init<<<N_NODES, NHID>>>(x, out);                               // 2
    k_zero_int2<<<(N_NODES + 255) / 256, 256>>>(deg_p, cur_p, N_NODES); // 3
    k_gemm<<<ggrid, 256, GEMM_SMEM>>>(att_src, att_dst);             // 4 (layer 0)
    k_count_deg<<<(ETOT + 255) / 256, 256>>>(dst);                   // 5
    k_scan<<<1, 1024>>>();                                           // 6
    k_scatter<<<(ETOT + 255) / 256, 256>>>(src, dst);                // 7
    k_aggregate<<<N_NODES, 64>>>(bias, out, 0);                      // 8 (layer 0)

    for (int l = 1; l < NLAYERS; l++) {
        k_gemm<<<ggrid, 256, GEMM_SMEM>>>(att_src, att_dst);
        k_aggregate<<<N_NODES, 64>>>(bias, out, l);
    }
    k_outproj<<<N_NODES, 128>>>(Wr, br, out);
}

// round 10
// speedup vs baseline: 1.2406x; 1.1083x over previous
#include <cuda_runtime.h>
#include <cuda_fp16.h>
#include <math.h>

#define N_NODES 20000
#define NHID 128
#define HEADS 4
#define HC (HEADS * NHID)          // 512
#define E_EDGES 320000
#define ETOT (E_EDGES + N_NODES)   // 340000
#define NLAYERS 4
#define NCLASS 40
#define NEG_SLOPE 0.2f
#define DT 1.0f
#define ALPHA 1.0f
#define GAMMA 1.0f

// d_out layout: [out (N*NCLASS)] [X_all (N*(L+1)*C)] [Y_all (N*(L+1)*C)]
#define OUT_OFF   0
#define XALL_OFF  (N_NODES * NCLASS)
#define YALL_OFF  (XALL_OFF + N_NODES * (NLAYERS + 1) * NHID)
#define LSTRIDE   ((NLAYERS + 1) * NHID)

// ------------------------- device scratch (no allocs allowed) ----------------
__device__ __half g_hh[N_NODES * HC];        // fp16 messages
__device__ float  g_X[N_NODES * NHID];
__device__ float  g_Y[N_NODES * NHID];
__device__ __half g_Xhi[N_NODES * NHID];     // double-fp16 split X (GEMM A)
__device__ __half g_Xlo[N_NODES * NHID];
__device__ __half g_Whi[HC * NHID];          // split W, TRANSPOSED [n][k]
__device__ __half g_Wlo[HC * NHID];
__device__ float  g_as[N_NODES * HEADS];
__device__ float  g_ad[N_NODES * HEADS];
__device__ int    g_deg[N_NODES];
__device__ int    g_cursor[N_NODES];
__device__ int    g_off[N_NODES + 1];
__device__ int    g_csr_src[ETOT];

__device__ __forceinline__ void mma_f16(float* c, const unsigned* a, const unsigned* b) {
    asm volatile(
        "mma.sync.aligned.m16n8k16.row.col.f32.f16.f16.f32 "
        "{%0,%1,%2,%3}, {%4,%5,%6,%7}, {%8,%9}, {%0,%1,%2,%3};\n"
        : "+f"(c[0]), "+f"(c[1]), "+f"(c[2]), "+f"(c[3])
        : "r"(a[0]), "r"(a[1]), "r"(a[2]), "r"(a[3]), "r"(b[0]), "r"(b[1]));
}

// ------------------------- setup kernels -------------------------------------
// split W (fp16 hi/lo, transposed to [n][k]) + zero deg/cursor. 65536 threads.
__global__ void k_splitW(const float* __restrict__ W) {
    int i = blockIdx.x * blockDim.x + threadIdx.x;   // 0..65535
    float w = W[i];
    __half hi = __float2half_rn(w);
    __half lo = __float2half_rn(w - __half2float(hi));
    int k = i >> 9;          // W is [128][512] row-major
    int n = i & 511;
    g_Whi[n * NHID + k] = hi;
    g_Wlo[n * NHID + k] = lo;
    if (i < N_NODES) { g_deg[i] = 0; g_cursor[i] = 0; }
}

__global__ void k_count_deg(const int* __restrict__ dst) {
    int e = blockIdx.x * blockDim.x + threadIdx.x;
    if (e >= ETOT) return;
    int d = (e < E_EDGES) ? dst[e] : (e - E_EDGES);
    atomicAdd(&g_deg[d], 1);
}

__global__ void k_scan() {
    __shared__ int s[1024];
    const int CH = (N_NODES + 1023) / 1024;
    int tid = threadIdx.x;
    int base = tid * CH;
    int sum = 0;
    for (int i = 0; i < CH; i++) {
        int idx = base + i;
        if (idx < N_NODES) sum += g_deg[idx];
    }
    s[tid] = sum;
    __syncthreads();
    for (int d = 1; d < 1024; d <<= 1) {
        int v = (tid >= d) ? s[tid - d] : 0;
        __syncthreads();
        s[tid] += v;
        __syncthreads();
    }
    int run = (tid == 0) ? 0 : s[tid - 1];
    for (int i = 0; i < CH; i++) {
        int idx = base + i;
        if (idx < N_NODES) { g_off[idx] = run; run += g_deg[idx]; }
    }
    if (tid == 1023) g_off[N_NODES] = run;
}

__global__ void k_scatter(const int* __restrict__ src, const int* __restrict__ dst) {
    int e = blockIdx.x * blockDim.x + threadIdx.x;
    if (e >= ETOT) return;
    int d, s;
    if (e < E_EDGES) { d = dst[e]; s = src[e]; }
    else { d = e - E_EDGES; s = d; }
    int pos = g_off[d] + atomicAdd(&g_cursor[d], 1);
    g_csr_src[pos] = s;
}

// init state (+ split X to fp16 hi/lo) + write layer-0 slices
__global__ void k_init(const float* __restrict__ x, float* __restrict__ out) {
    int n = blockIdx.x;
    int t = threadIdx.x;
    float v = x[n * NHID + t];
    g_X[n * NHID + t] = v;
    g_Y[n * NHID + t] = v;
    __half hi = __float2half_rn(v);
    g_Xhi[n * NHID + t] = hi;
    g_Xlo[n * NHID + t] = __float2half_rn(v - __half2float(hi));
    out[XALL_OFF + n * LSTRIDE + t] = v;
    out[YALL_OFF + n * LSTRIDE + t] = v;
}

// ------------------------- 3x split-FP16 tensor GEMM + fused attention --------
// C = X @ W, 128x128 tile, BK=32 halves, m16n8k16 f16 MMA with fp32 accum.
// hi*hi + hi*lo + lo*hi => product error ~2^-22 (3xTF32-class accuracy).
// A [m][k], B [n][k] in smem, pitch 40 halves (80 B = 20 words): frag LDS.32
// banks = 20*r%32 + q -> all 32 distinct, conflict-free.
#define GBM 128
#define GBN 128
#define APH 40                      // pitch in halves

__global__ __launch_bounds__(256, 2) void k_gemm(const float* __restrict__ att_src,
                                                 const float* __restrict__ att_dst) {
    __shared__ __half Ah[128 * APH];
    __shared__ __half Al[128 * APH];
    __shared__ __half Bh[128 * APH];
    __shared__ __half Bl[128 * APH];

    int tid = threadIdx.x;
    int m0 = blockIdx.y * GBM;
    int n0 = blockIdx.x * GBN;      // = head * NHID
    int head = blockIdx.x;
    int warp = tid >> 5, lane = tid & 31;
    int g = lane >> 2, q = lane & 3;
    int wm = (warp >> 1) * 32;      // warp tile 32(m) x 64(n)
    int wn = (warp & 1) * 64;

    float acc[2][8][4];
#pragma unroll
    for (int mi = 0; mi < 2; mi++)
#pragma unroll
        for (int ni = 0; ni < 8; ni++)
#pragma unroll
            for (int j = 0; j < 4; j++) acc[mi][ni][j] = 0.f;

    for (int st = 0; st < 4; st++) {
        __syncthreads();
        // A stage: 128 rows x 32 halves per buffer (4 uint4/row)
#pragma unroll
        for (int i = 0; i < 2; i++) {
            int idx = tid + i * 256;        // 0..511
            int r = idx >> 2, c8 = idx & 3;
            uint4 vh = make_uint4(0, 0, 0, 0), vl = vh;
            if (m0 + r < N_NODES) {
                const __half* ph = g_Xhi + (m0 + r) * NHID + st * 32 + c8 * 8;
                const __half* pl = g_Xlo + (m0 + r) * NHID + st * 32 + c8 * 8;
                vh = *(const uint4*)ph;
                vl = *(const uint4*)pl;
            }
            *(uint4*)&Ah[r * APH + c8 * 8] = vh;
            *(uint4*)&Al[r * APH + c8 * 8] = vl;
        }
        // B stage: 128 n-rows x 32 halves per buffer
#pragma unroll
        for (int i = 0; i < 2; i++) {
            int idx = tid + i * 256;
            int r = idx >> 2, c8 = idx & 3;
            const __half* ph = g_Whi + (n0 + r) * NHID + st * 32 + c8 * 8;
            const __half* pl = g_Wlo + (n0 + r) * NHID + st * 32 + c8 * 8;
            *(uint4*)&Bh[r * APH + c8 * 8] = *(const uint4*)ph;
            *(uint4*)&Bl[r * APH + c8 * 8] = *(const uint4*)pl;
        }
        __syncthreads();

#pragma unroll
        for (int ks = 0; ks < 2; ks++) {
            int kb = ks * 16;
            unsigned ah[2][4], al[2][4];
#pragma unroll
            for (int mi = 0; mi < 2; mi++) {
                int r = wm + mi * 16 + g;
                ah[mi][0] = *(const unsigned*)&Ah[r * APH + kb + 2 * q];
                ah[mi][1] = *(const unsigned*)&Ah[(r + 8) * APH + kb + 2 * q];
                ah[mi][2] = *(const unsigned*)&Ah[r * APH + kb + 2 * q + 8];
                ah[mi][3] = *(const unsigned*)&Ah[(r + 8) * APH + kb + 2 * q + 8];
                al[mi][0] = *(const unsigned*)&Al[r * APH + kb + 2 * q];
                al[mi][1] = *(const unsigned*)&Al[(r + 8) * APH + kb + 2 * q];
                al[mi][2] = *(const unsigned*)&Al[r * APH + kb + 2 * q + 8];
                al[mi][3] = *(const unsigned*)&Al[(r + 8) * APH + kb + 2 * q + 8];
            }
#pragma unroll
            for (int ni = 0; ni < 8; ni++) {
                int c = wn + ni * 8 + g;
                unsigned bh[2], bl[2];
                bh[0] = *(const unsigned*)&Bh[c * APH + kb + 2 * q];
                bh[1] = *(const unsigned*)&Bh[c * APH + kb + 2 * q + 8];
                bl[0] = *(const unsigned*)&Bl[c * APH + kb + 2 * q];
                bl[1] = *(const unsigned*)&Bl[c * APH + kb + 2 * q + 8];
#pragma unroll
                for (int mi = 0; mi < 2; mi++) {
                    mma_f16(acc[mi][ni], ah[mi], bh);   // hi*hi
                    mma_f16(acc[mi][ni], ah[mi], bl);   // hi*lo
                    mma_f16(acc[mi][ni], al[mi], bh);   // lo*hi
                }
            }
        }
    }

    __syncthreads();                    // mainloop done; reuse B buffers
    float* sAs = (float*)Bh;            // [2][128]
    float* sAd = ((float*)Bh) + 256;

    float attS[16], attD[16];
#pragma unroll
    for (int ni = 0; ni < 8; ni++) {
        int c = n0 + wn + ni * 8 + 2 * q;
        attS[2 * ni] = att_src[c];     attS[2 * ni + 1] = att_src[c + 1];
        attD[2 * ni] = att_dst[c];     attD[2 * ni + 1] = att_dst[c + 1];
    }
#pragma unroll
    for (int mi = 0; mi < 2; mi++) {
        float s1a = 0.f, s2a = 0.f, s1b = 0.f, s2b = 0.f;
#pragma unroll
        for (int ni = 0; ni < 8; ni++) {
            s1a += acc[mi][ni][0] * attS[2 * ni] + acc[mi][ni][1] * attS[2 * ni + 1];
            s2a += acc[mi][ni][0] * attD[2 * ni] + acc[mi][ni][1] * attD[2 * ni + 1];
            s1b += acc[mi][ni][2] * attS[2 * ni] + acc[mi][ni][3] * attS[2 * ni + 1];
            s2b += acc[mi][ni][2] * attD[2 * ni] + acc[mi][ni][3] * attD[2 * ni + 1];
        }
#pragma unroll
        for (int o = 2; o; o >>= 1) {
            s1a += __shfl_down_sync(0xffffffffu, s1a, o, 4);
            s2a += __shfl_down_sync(0xffffffffu, s2a, o, 4);
            s1b += __shfl_down_sync(0xffffffffu, s1b, o, 4);
            s2b += __shfl_down_sync(0xffffffffu, s2b, o, 4);
        }
        if (q == 0) {
            int half = warp & 1;
            int rA = wm + mi * 16 + g;
            sAs[half * 128 + rA] = s1a;      sAd[half * 128 + rA] = s2a;
            sAs[half * 128 + rA + 8] = s1b;  sAd[half * 128 + rA + 8] = s2b;
        }
    }
    __syncthreads();
    if (tid < 128) {
        int r = m0 + tid;
        if (r < N_NODES) {
            g_as[r * HEADS + head] = sAs[tid] + sAs[128 + tid];
            g_ad[r * HEADS + head] = sAd[tid] + sAd[128 + tid];
        }
    }

    // store h as fp16
#pragma unroll
    for (int mi = 0; mi < 2; mi++) {
        int r = m0 + wm + mi * 16 + g;
#pragma unroll
        for (int ni = 0; ni < 8; ni++) {
            int c = n0 + wn + ni * 8 + 2 * q;
            if (r < N_NODES)
                *((__half2*)(g_hh + r * HC + c)) = __floats2half2_rn(acc[mi][ni][0], acc[mi][ni][1]);
            if (r + 8 < N_NODES)
                *((__half2*)(g_hh + (r + 8) * HC + c)) = __floats2half2_rn(acc[mi][ni][2], acc[mi][ni][3]);
        }
    }
}

// ------------------------- fused softmax + aggregate + GraphCON update --------
// 64 threads/node; thread t owns fp16 flat channels [8t..8t+7] (head t/16).
#define ACH 64
__global__ __launch_bounds__(64) void k_aggregate(const float* __restrict__ bias,
                                                  float* __restrict__ out, int layer) {
    __shared__ int   s_src[ACH];
    __shared__ float s_ex[ACH * 4];
    __shared__ float4 s_den[2];

    int n = blockIdx.x;
    int t = threadIdx.x;
    int hd = t >> 4;
    int wid = t >> 5, lane = t & 31;
    int st = g_off[n], en = g_off[n + 1];
    float4 ad4 = ((const float4*)g_ad)[n];
    const uint4* h16 = (const uint4*)g_hh;

    float4 denp = make_float4(0.f, 0.f, 0.f, 0.f);
    float a0 = 0.f, a1 = 0.f, a2 = 0.f, a3 = 0.f;
    float a4 = 0.f, a5 = 0.f, a6 = 0.f, a7 = 0.f;

#define ACCUM(u, e) { \
    float2 p0 = __half22float2(*(const __half2*)&u.x); \
    float2 p1 = __half22float2(*(const __half2*)&u.y); \
    float2 p2 = __half22float2(*(const __half2*)&u.z); \
    float2 p3 = __half22float2(*(const __half2*)&u.w); \
    a0 += e * p0.x; a1 += e * p0.y; a2 += e * p1.x; a3 += e * p1.y; \
    a4 += e * p2.x; a5 += e * p2.y; a6 += e * p3.x; a7 += e * p3.y; }

    for (int c0 = st; c0 < en; c0 += ACH) {
        int cl = en - c0; if (cl > ACH) cl = ACH;
        if (t < cl) {
            int s = g_csr_src[c0 + t];
            float4 as4 = ((const float4*)g_as)[s];
            float e0 = as4.x + ad4.x, e1 = as4.y + ad4.y;
            float e2 = as4.z + ad4.z, e3 = as4.w + ad4.w;
            e0 = e0 > 0.f ? e0 : e0 * NEG_SLOPE;
            e1 = e1 > 0.f ? e1 : e1 * NEG_SLOPE;
            e2 = e2 > 0.f ? e2 : e2 * NEG_SLOPE;
            e3 = e3 > 0.f ? e3 : e3 * NEG_SLOPE;
            float x0 = __expf(e0), x1 = __expf(e1), x2 = __expf(e2), x3 = __expf(e3);
            s_src[t] = s;
            ((float4*)s_ex)[t] = make_float4(x0, x1, x2, x3);
            denp.x += x0; denp.y += x1; denp.z += x2; denp.w += x3;
        }
        __syncthreads();
        int j = 0;
        for (; j + 8 <= cl; j += 8) {
            int ss[8]; float ee[8]; uint4 uu[8];
#pragma unroll
            for (int u = 0; u < 8; u++) {
                ss[u] = s_src[j + u];
                ee[u] = s_ex[(j + u) * 4 + hd];
            }
#pragma unroll
            for (int u = 0; u < 8; u++) uu[u] = h16[ss[u] * 64 + t];
#pragma unroll
            for (int u = 0; u < 8; u++) ACCUM(uu[u], ee[u])
        }
        for (; j < cl; j++) {
            int s = s_src[j];
            float e = s_ex[j * 4 + hd];
            uint4 u = h16[s * 64 + t];
            ACCUM(u, e)
        }
        __syncthreads();
    }
#undef ACCUM

#pragma unroll
    for (int o = 16; o; o >>= 1) {
        denp.x += __shfl_xor_sync(0xffffffffu, denp.x, o);
        denp.y += __shfl_xor_sync(0xffffffffu, denp.y, o);
        denp.z += __shfl_xor_sync(0xffffffffu, denp.z, o);
        denp.w += __shfl_xor_sync(0xffffffffu, denp.w, o);
    }
    if (lane == 0) s_den[wid] = denp;
    __syncthreads();
    float4 d0 = s_den[0], d1 = s_den[1];
    float dens[4] = {d0.x + d1.x, d0.y + d1.y, d0.z + d1.z, d0.w + d1.w};
    float inv = 1.0f / dens[hd];

    const float4* b4p = (const float4*)(bias + 8 * t);
    float4 b0 = b4p[0], b1 = b4p[1];
    float g0 = a0 * inv + b0.x, g1 = a1 * inv + b0.y;
    float g2 = a2 * inv + b0.z, g3 = a3 * inv + b0.w;
    float g4 = a4 * inv + b1.x, g5 = a5 * inv + b1.y;
    float g6 = a6 * inv + b1.z, g7 = a7 * inv + b1.w;
    g0 = g0 > 0.f ? g0 : (expf(g0) - 1.f);
    g1 = g1 > 0.f ? g1 : (expf(g1) - 1.f);
    g2 = g2 > 0.f ? g2 : (expf(g2) - 1.f);
    g3 = g3 > 0.f ? g3 : (expf(g3) - 1.f);
    g4 = g4 > 0.f ? g4 : (expf(g4) - 1.f);
    g5 = g5 > 0.f ? g5 : (expf(g5) - 1.f);
    g6 = g6 > 0.f ? g6 : (expf(g6) - 1.f);
    g7 = g7 > 0.f ? g7 : (expf(g7) - 1.f);
    float aggA = 0.25f * (g0 + g1 + g2 + g3);
    float aggB = 0.25f * (g4 + g5 + g6 + g7);

    float2 xv = *((const float2*)(g_X + n * NHID + 2 * t));
    float2 yv = *((const float2*)(g_Y + n * NHID + 2 * t));
    float y2a = yv.x + DT * (aggA - ALPHA * yv.x - GAMMA * xv.x);
    float y2b = yv.y + DT * (aggB - ALPHA * yv.y - GAMMA * xv.y);
    float x2a = xv.x + DT * y2a;
    float x2b = xv.y + DT * y2b;
    *((float2*)(g_X + n * NHID + 2 * t)) = make_float2(x2a, x2b);
    *((float2*)(g_Y + n * NHID + 2 * t)) = make_float2(y2a, y2b);

    // split X to fp16 hi/lo for next layer's GEMM
    __half hA = __float2half_rn(x2a), hB = __float2half_rn(x2b);
    __half lA = __float2half_rn(x2a - __half2float(hA));
    __half lB = __float2half_rn(x2b - __half2float(hB));
    *((__half2*)(g_Xhi + n * NHID + 2 * t)) = __halves2half2(hA, hB);
    *((__half2*)(g_Xlo + n * NHID + 2 * t)) = __halves2half2(lA, lB);

    float* xo = out + XALL_OFF + n * LSTRIDE + (layer + 1) * NHID + 2 * t;
    float* yo = out + YALL_OFF + n * LSTRIDE + (layer + 1) * NHID + 2 * t;
    *((float2*)xo) = make_float2(x2a, x2b);
    *((float2*)yo) = make_float2(y2a, y2b);
}

// ------------------------- output projection ----------------------------------
__global__ void k_outproj(const float* __restrict__ Wr, const float* __restrict__ br,
                          float* __restrict__ out) {
    __shared__ float xs[NHID];
    int n = blockIdx.x;
    int t = threadIdx.x;
    xs[t] = g_X[n * NHID + t];
    __syncthreads();
    if (t < NCLASS) {
        const float* w = Wr + t * NHID;
        float acc = 0.f;
#pragma unroll 8
        for (int k = 0; k < NHID; k++) acc += xs[k] * w[k];
        out[OUT_OFF + n * NCLASS + t] = acc + br[t];
    }
}

// ------------------------- launch ---------------------------------------------
extern "C" void kernel_launch(void* const* d_in, const int* in_sizes, int n_in,
                              void* d_out, int out_size) {
    const float* x       = (const float*)d_in[0];
    const int*   src     = (const int*)d_in[1];
    const int*   dst     = (const int*)d_in[2];
    const float* W       = (const float*)d_in[3];
    const float* att_src = (const float*)d_in[4];
    const float* att_dst = (const float*)d_in[5];
    const float* bias    = (const float*)d_in[6];
    const float* Wr      = (const float*)d_in[7];
    const float* br      = (const float*)d_in[8];
    float* out = (float*)d_out;

    dim3 ggrid(HC / GBN, (N_NODES + GBM - 1) / GBM);   // (4, 157)

    // gemm in capture slot 4 for ncu. deps: splitW zeros deg/cursor before
    // count; gemm needs splitW + init; agg needs scatter + gemm.
    k_splitW<<<(NHID * HC) / 256, 256>>>(W);                 // 1 (also zeros)
    k_init<<<N_NODES, NHID>>>(x, out);                       // 2
    k_count_deg<<<(ETOT + 255) / 256, 256>>>(dst);           // 3
    k_gemm<<<ggrid, 256>>>(att_src, att_dst);                // 4 (layer 0)
    k_scan<<<1, 1024>>>();                                   // 5
    k_scatter<<<(ETOT + 255) / 256, 256>>>(src, dst);        // 6
    k_aggregate<<<N_NODES, 64>>>(bias, out, 0);              // 7 (layer 0)

    for (int l = 1; l < NLAYERS; l++) {
        k_gemm<<<ggrid, 256>>>(att_src, att_dst);
        k_aggregate<<<N_NODES, 64>>>(bias, out, l);
    }
    k_outproj<<<N_NODES, 128>>>(Wr, br, out);
}